// round 12
// baseline (speedup 1.0000x reference)
#include <cuda_runtime.h>
#include <cuda_bf16.h>
#include <math.h>
#include <stdint.h>

// ---------------- problem constants ----------------
constexpr int kN0Src = 400000, kN0Dst = 32000, kE0 = 320000;
constexpr int kN1Src = 32000,  kN1Dst = 3200,  kE1 = 32000;
constexpr int kN2Src = 3200,   kN2Dst = 1024,  kE2 = 10240;
constexpr int kInF = 256, kHid = 256, kNCls = 47;
constexpr int kNDstTot = kN0Dst + kN1Dst + kN2Dst;

// ---------------- device scratch (no allocs allowed) ----------------
__device__ __align__(256) float g_h0  [kN0Dst * kHid];
__device__ __align__(256) float g_h1  [kN1Dst * kHid];
__device__ __align__(256) float g_agg2[kN2Dst * kHid];

__device__ __align__(256) __nv_bfloat16 g_w0h[kHid * kHid], g_w0l[kHid * kHid];
__device__ __align__(256) __nv_bfloat16 g_w1h[kHid * kHid], g_w1l[kHid * kHid];

__device__ __align__(256) int g_cnt[2 * kNDstTot];   // deg | cur, one memset
__device__ int g_off0[kN0Dst + 1], g_es0[kE0];
__device__ int g_off1[kN1Dst + 1], g_es1[kE1];
__device__ int g_off2[kN2Dst + 1], g_es2[kE2];
__device__ int g_bsum[37];

// ---------------- helpers ----------------
__device__ __forceinline__ uint32_t smem_u32(const void* p) {
    uint32_t a;
    asm("{ .reg .u64 t; cvta.to.shared.u64 t, %1; cvt.u32.u64 %0, t; }" : "=r"(a) : "l"(p));
    return a;
}

__device__ __forceinline__ void ldsm_x4(uint32_t& r0, uint32_t& r1, uint32_t& r2,
                                        uint32_t& r3, uint32_t addr) {
    asm volatile("ldmatrix.sync.aligned.m8n8.x4.shared.b16 {%0,%1,%2,%3}, [%4];"
                 : "=r"(r0), "=r"(r1), "=r"(r2), "=r"(r3) : "r"(addr));
}

__device__ __forceinline__ void mma16816(float c[4], uint32_t a0, uint32_t a1,
                                         uint32_t a2, uint32_t a3,
                                         uint32_t b0, uint32_t b1) {
    asm volatile(
        "mma.sync.aligned.m16n8k16.row.col.f32.bf16.bf16.f32 "
        "{%0,%1,%2,%3},{%4,%5,%6,%7},{%8,%9},{%0,%1,%2,%3};"
        : "+f"(c[0]), "+f"(c[1]), "+f"(c[2]), "+f"(c[3])
        : "r"(a0), "r"(a1), "r"(a2), "r"(a3), "r"(b0), "r"(b1));
}

__device__ __forceinline__ uint32_t swz(uint32_t x) { return x ^ ((x >> 3) & 0x70); }
// K-major SW128 blocked-atom byte offset for a [128 rows][256 k] bf16 tile:
// block kc = k>>6 occupies 16KB; within a block it's row*128 + (k&63)*2.
__device__ __forceinline__ uint32_t kmaj(int row, int k) {
    return (uint32_t)(((k >> 6) << 14) + (row << 7) + ((k & 63) << 1));
}

// ---------------- CSR build ----------------
__global__ void hist3_kernel(const int* __restrict__ d0, const int* __restrict__ d1,
                             const int* __restrict__ d2) {
    int i = blockIdx.x * blockDim.x + threadIdx.x;
    if (i < kE0) atomicAdd(&g_cnt[d0[i]], 1);
    if (i < kE1) atomicAdd(&g_cnt[kN0Dst + d1[i]], 1);
    if (i < kE2) atomicAdd(&g_cnt[kN0Dst + kN1Dst + d2[i]], 1);
}

__global__ void exscanA_kernel() {
    __shared__ int warp_sums[32];
    int b = blockIdx.x;
    const int* cnt; int* off; int n, lb;
    if (b < 32)      { cnt = g_cnt;                    off = g_off0; n = kN0Dst; lb = b; }
    else if (b < 36) { cnt = g_cnt + kN0Dst;           off = g_off1; n = kN1Dst; lb = b - 32; }
    else             { cnt = g_cnt + kN0Dst + kN1Dst;  off = g_off2; n = kN2Dst; lb = 0; }
    int tid = threadIdx.x, lane = tid & 31, wid = tid >> 5;
    int idx = lb * 1024 + tid;
    int orig = (idx < n) ? cnt[idx] : 0;
    int v = orig;
    #pragma unroll
    for (int d = 1; d < 32; d <<= 1) {
        int t = __shfl_up_sync(0xffffffffu, v, d);
        if (lane >= d) v += t;
    }
    if (lane == 31) warp_sums[wid] = v;
    __syncthreads();
    if (wid == 0) {
        int w = warp_sums[lane];
        #pragma unroll
        for (int d = 1; d < 32; d <<= 1) {
            int t = __shfl_up_sync(0xffffffffu, w, d);
            if (lane >= d) w += t;
        }
        warp_sums[lane] = w;
    }
    __syncthreads();
    int incl = v + ((wid > 0) ? warp_sums[wid - 1] : 0);
    if (idx < n) off[idx] = incl - orig;
    if (tid == 1023) g_bsum[b] = incl;
}

__global__ void exscanB_kernel() {
    __shared__ int s_prefix, s_total;
    int b = blockIdx.x;
    int* off; int n, lb, base, nb;
    if (b < 32)      { off = g_off0; n = kN0Dst; base = 0;  nb = 32; lb = b; }
    else if (b < 36) { off = g_off1; n = kN1Dst; base = 32; nb = 4;  lb = b - 32; }
    else             { off = g_off2; n = kN2Dst; base = 36; nb = 1;  lb = 0; }
    int tid = threadIdx.x;
    if (tid < 32) {
        int v = (tid < nb) ? g_bsum[base + tid] : 0;
        int incl = v;
        #pragma unroll
        for (int d = 1; d < 32; d <<= 1) {
            int t = __shfl_up_sync(0xffffffffu, incl, d);
            if (tid >= d) incl += t;
        }
        if (tid == lb)     s_prefix = incl - v;
        if (tid == nb - 1) s_total  = incl;
    }
    __syncthreads();
    int idx = lb * 1024 + tid;
    if (idx < n) off[idx] += s_prefix;
    if (lb == nb - 1 && tid == 1023) off[n] = s_total;
}

__global__ void fill3_kernel(const int* __restrict__ s0, const int* __restrict__ d0,
                             const int* __restrict__ s1, const int* __restrict__ d1,
                             const int* __restrict__ s2, const int* __restrict__ d2) {
    int i = blockIdx.x * blockDim.x + threadIdx.x;
    int* cur = g_cnt + kNDstTot;
    if (i < kE0) { int d = d0[i]; int p = atomicAdd(&cur[d], 1);
                   g_es0[g_off0[d] + p] = s0[i]; }
    if (i < kE1) { int d = d1[i]; int p = atomicAdd(&cur[kN0Dst + d], 1);
                   g_es1[g_off1[d] + p] = s1[i]; }
    if (i < kE2) { int d = d2[i]; int p = atomicAdd(&cur[kN0Dst + kN1Dst + d], 1);
                   g_es2[g_off2[d] + p] = s2[i]; }
}

// ---------------- weight transpose + bf16 hi/lo split -------------------------
__global__ void wconv_kernel(const float* __restrict__ W0, const float* __restrict__ W1) {
    int i = blockIdx.x * blockDim.x + threadIdx.x;
    const float* W = (i < 65536) ? W0 : W1;
    __nv_bfloat16* wh = (i < 65536) ? g_w0h : g_w1h;
    __nv_bfloat16* wl = (i < 65536) ? g_w0l : g_w1l;
    int j = i & 65535;
    int k = j >> 8, n = j & 255;
    float v = W[j];
    __nv_bfloat16 hi = __float2bfloat16(v);
    __nv_bfloat16 lo = __float2bfloat16(v - __bfloat162float(hi));
    wh[n * 256 + k] = hi;
    wl[n * 256 + k] = lo;
}

// ---------------- standalone aggregation (layer 2, f32 out) -------------------
__global__ void aggregate_f32_kernel(const float* __restrict__ feat, const int* __restrict__ off,
                                     const int* __restrict__ esrc, float* __restrict__ aggf,
                                     int n_dst) {
    int warp = (blockIdx.x * blockDim.x + threadIdx.x) >> 5;
    int lane = threadIdx.x & 31;
    if (warp >= n_dst) return;
    int s = off[warp], e = off[warp + 1];
    float4 a0 = make_float4(0.f, 0.f, 0.f, 0.f);
    float4 a1 = make_float4(0.f, 0.f, 0.f, 0.f);
    for (int i = s; i < e; i += 2) {
        int j0 = __ldg(esrc + i);
        bool two = (i + 1 < e);
        int j1 = two ? __ldg(esrc + i + 1) : j0;
        const float4* r0p = (const float4*)(feat + (size_t)j0 * 256);
        const float4* r1p = (const float4*)(feat + (size_t)j1 * 256);
        float4 u0 = __ldg(&r0p[lane]);
        float4 u1 = __ldg(&r0p[lane + 32]);
        float4 w0 = __ldg(&r1p[lane]);
        float4 w1 = __ldg(&r1p[lane + 32]);
        a0.x += u0.x; a0.y += u0.y; a0.z += u0.z; a0.w += u0.w;
        a1.x += u1.x; a1.y += u1.y; a1.z += u1.z; a1.w += u1.w;
        if (two) {
            a0.x += w0.x; a0.y += w0.y; a0.z += w0.z; a0.w += w0.w;
            a1.x += w1.x; a1.y += w1.y; a1.z += w1.z; a1.w += w1.w;
        }
    }
    int deg = e - s;
    float inv = 1.0f / (float)(deg > 1 ? deg : 1);
    a0.x *= inv; a0.y *= inv; a0.z *= inv; a0.w *= inv;
    a1.x *= inv; a1.y *= inv; a1.z *= inv; a1.w *= inv;
    float4* dp = (float4*)(aggf + (size_t)warp * 256);
    dp[lane]      = a0;
    dp[lane + 32] = a1;
}

// ---------------- FUSED aggregate + bf16-split GEMM + bias + relu -------------
// CTA = 128 dst rows x full N=256. 512 threads = 16 warps (4M x 4N), warp 32x64.
// Phase 1: warp w aggregates rows [w*8, w*8+8), writes bf16 hi/lo into SW128 smem.
// Phase 2: 4 K-chunks; per chunk load weight slice [256n][64k] hi/lo, ldsm+mma.
constexpr int FA_HI = 0;        // A hi: [128][256] bf16 kmaj = 64KB
constexpr int FA_LO = 65536;    // A lo: 64KB
constexpr int FB_HI = 131072;   // B hi chunk: [256][64] bf16 = 32KB
constexpr int FB_LO = 163840;   // B lo chunk: 32KB
constexpr int kFusedSmem = 196608;

__global__ void __launch_bounds__(512)
fused_layer_kernel(const float* __restrict__ feat, const int* __restrict__ off,
                   const int* __restrict__ esrc,
                   const __nv_bfloat16* __restrict__ Bh, const __nv_bfloat16* __restrict__ Bl,
                   const float* __restrict__ bias, float* __restrict__ C) {
    extern __shared__ char smem[];
    uint32_t sb = smem_u32(smem);
    int tid = threadIdx.x, warp = tid >> 5, lane = tid & 31;
    int m0 = blockIdx.x * 128;

    // ---- phase 1: aggregate 8 rows per warp into smem (bf16 hi/lo, kmaj+swz) ----
    #pragma unroll 1
    for (int rr = 0; rr < 8; rr++) {
        int row = warp * 8 + rr;          // local row 0..127
        int g = m0 + row;
        int s = off[g], e = off[g + 1];
        float4 a0 = make_float4(0.f, 0.f, 0.f, 0.f);
        float4 a1 = make_float4(0.f, 0.f, 0.f, 0.f);
        for (int i = s; i < e; i += 2) {
            int j0 = __ldg(esrc + i);
            bool two = (i + 1 < e);
            int j1 = two ? __ldg(esrc + i + 1) : j0;
            const float4* r0p = (const float4*)(feat + (size_t)j0 * 256);
            const float4* r1p = (const float4*)(feat + (size_t)j1 * 256);
            float4 u0 = __ldg(&r0p[lane]);
            float4 u1 = __ldg(&r0p[lane + 32]);
            float4 w0 = __ldg(&r1p[lane]);
            float4 w1 = __ldg(&r1p[lane + 32]);
            a0.x += u0.x; a0.y += u0.y; a0.z += u0.z; a0.w += u0.w;
            a1.x += u1.x; a1.y += u1.y; a1.z += u1.z; a1.w += u1.w;
            if (two) {
                a0.x += w0.x; a0.y += w0.y; a0.z += w0.z; a0.w += w0.w;
                a1.x += w1.x; a1.y += w1.y; a1.z += w1.z; a1.w += w1.w;
            }
        }
        int deg = e - s;
        float inv = 1.0f / (float)(deg > 1 ? deg : 1);
        a0.x *= inv; a0.y *= inv; a0.z *= inv; a0.w *= inv;
        a1.x *= inv; a1.y *= inv; a1.z *= inv; a1.w *= inv;
        float v[8] = {a0.x, a0.y, a0.z, a0.w, a1.x, a1.y, a1.z, a1.w};
        #pragma unroll
        for (int g2 = 0; g2 < 2; g2++) {
            int k = g2 * 128 + lane * 4;
            __nv_bfloat162 h01, h23, l01, l23;
            h01.x = __float2bfloat16(v[g2*4+0]); h01.y = __float2bfloat16(v[g2*4+1]);
            h23.x = __float2bfloat16(v[g2*4+2]); h23.y = __float2bfloat16(v[g2*4+3]);
            l01.x = __float2bfloat16(v[g2*4+0] - __bfloat162float(h01.x));
            l01.y = __float2bfloat16(v[g2*4+1] - __bfloat162float(h01.y));
            l23.x = __float2bfloat16(v[g2*4+2] - __bfloat162float(h23.x));
            l23.y = __float2bfloat16(v[g2*4+3] - __bfloat162float(h23.y));
            uint32_t o = swz(kmaj(row, k));
            *(__nv_bfloat162*)(smem + FA_HI + o)     = h01;
            *(__nv_bfloat162*)(smem + FA_HI + o + 4) = h23;
            *(__nv_bfloat162*)(smem + FA_LO + o)     = l01;
            *(__nv_bfloat162*)(smem + FA_LO + o + 4) = l23;
        }
    }
    __syncthreads();

    // ---- phase 2: GEMM ----
    int wm = (warp & 3) * 32;
    int wn = (warp >> 2) * 64;

    float acc[2][8][4];
    #pragma unroll
    for (int i = 0; i < 2; i++)
        #pragma unroll
        for (int j = 0; j < 8; j++)
            #pragma unroll
            for (int q = 0; q < 4; q++) acc[i][j][q] = 0.f;

    uint32_t xorv = (uint32_t)(lane & 7) << 4;
    int rowA = wm + (lane & 7) + ((lane >> 3) & 1) * 8;
    uint32_t kbA = ((lane >> 4) & 1) << 4;
    uint32_t pA0 = sb + FA_HI + (uint32_t)(rowA)      * 128;
    uint32_t pA1 = sb + FA_HI + (uint32_t)(rowA + 16) * 128;
    int rowB = wn + (lane & 7) + ((lane >> 4) & 1) * 8;
    uint32_t kbB = ((lane >> 3) & 1) << 4;
    uint32_t pB[4];
    #pragma unroll
    for (int j16 = 0; j16 < 4; j16++)
        pB[j16] = sb + FB_HI + (uint32_t)(rowB + j16 * 16) * 128;

    #pragma unroll 1
    for (int kc = 0; kc < 4; kc++) {
        // load weight chunk [256 n][64 k] hi/lo into smem
        #pragma unroll
        for (int u = tid; u < 2048; u += 512) {
            int row = u >> 3;                         // 0..255
            uint32_t c16 = (u & 7) << 4;
            uint32_t so = (uint32_t)row * 128 + (c16 ^ ((row & 7) << 4));
            size_t gb = (size_t)row * 256 + kc * 64 + (c16 >> 1);
            *(uint4*)(smem + FB_HI + so) = *(const uint4*)(Bh + gb);
            *(uint4*)(smem + FB_LO + so) = *(const uint4*)(Bl + gb);
        }
        __syncthreads();
        uint32_t stgA = (uint32_t)kc << 14;           // kc * 16384

        #pragma unroll
        for (int kk = 0; kk < 4; kk++) {
            uint32_t koA = (((uint32_t)kk * 32 + kbA) ^ xorv) + stgA;
            uint32_t koB = ((uint32_t)kk * 32 + kbB) ^ xorv;
            uint32_t ah[2][4], al[2][4];
            ldsm_x4(ah[0][0], ah[0][1], ah[0][2], ah[0][3], pA0 + koA);
            ldsm_x4(ah[1][0], ah[1][1], ah[1][2], ah[1][3], pA1 + koA);
            ldsm_x4(al[0][0], al[0][1], al[0][2], al[0][3], pA0 + 65536 + koA);
            ldsm_x4(al[1][0], al[1][1], al[1][2], al[1][3], pA1 + 65536 + koA);
            #pragma unroll
            for (int j16 = 0; j16 < 4; j16++) {
                uint32_t bh0, bh1, bh2, bh3, bl0, bl1, bl2, bl3;
                ldsm_x4(bh0, bh1, bh2, bh3, pB[j16] + koB);
                ldsm_x4(bl0, bl1, bl2, bl3, pB[j16] + 32768 + koB);
                #pragma unroll
                for (int i = 0; i < 2; i++) {
                    mma16816(acc[i][2*j16+0], ah[i][0], ah[i][1], ah[i][2], ah[i][3], bh0, bh1);
                    mma16816(acc[i][2*j16+0], al[i][0], al[i][1], al[i][2], al[i][3], bh0, bh1);
                    mma16816(acc[i][2*j16+0], ah[i][0], ah[i][1], ah[i][2], ah[i][3], bl0, bl1);
                    mma16816(acc[i][2*j16+1], ah[i][0], ah[i][1], ah[i][2], ah[i][3], bh2, bh3);
                    mma16816(acc[i][2*j16+1], al[i][0], al[i][1], al[i][2], al[i][3], bh2, bh3);
                    mma16816(acc[i][2*j16+1], ah[i][0], ah[i][1], ah[i][2], ah[i][3], bl2, bl3);
                }
            }
        }
        __syncthreads();
    }

    // ---- epilogue: bias + relu ----
    int qr = lane >> 2;
    int qc = (lane & 3) << 1;
    #pragma unroll
    for (int i = 0; i < 2; i++) {
        int r0 = m0 + wm + i * 16 + qr;
        #pragma unroll
        for (int j = 0; j < 8; j++) {
            int col = wn + j * 8 + qc;
            float b0 = __ldg(bias + col), b1 = __ldg(bias + col + 1);
            float2 v0, v1;
            v0.x = fmaxf(acc[i][j][0] + b0, 0.f);
            v0.y = fmaxf(acc[i][j][1] + b1, 0.f);
            v1.x = fmaxf(acc[i][j][2] + b0, 0.f);
            v1.y = fmaxf(acc[i][j][3] + b1, 0.f);
            *(float2*)(C + (size_t)r0 * 256 + col)       = v0;
            *(float2*)(C + (size_t)(r0 + 8) * 256 + col) = v1;
        }
    }
}

// ---------------- layer 2 + log_softmax ----------------
__global__ void layer2_logsoftmax_kernel(const float* __restrict__ agg,
                                         const float* __restrict__ W,
                                         const float* __restrict__ b,
                                         float* __restrict__ out) {
    __shared__ float a[256];
    __shared__ float logits[kNCls];
    __shared__ float s_ls;
    int row = blockIdx.x;
    int tid = threadIdx.x;
    const float4* ap = (const float4*)(agg + (size_t)row * 256);
    ((float4*)a)[tid] = ap[tid];
    __syncthreads();
    if (tid < kNCls) {
        float sum = b[tid];
        #pragma unroll 8
        for (int k = 0; k < 256; k++) sum += a[k] * W[k * kNCls + tid];
        logits[tid] = sum;
    }
    __syncthreads();
    if (tid == 0) {
        float m = -INFINITY;
        for (int j = 0; j < kNCls; j++) m = fmaxf(m, logits[j]);
        float s = 0.f;
        for (int j = 0; j < kNCls; j++) s += expf(logits[j] - m);
        s_ls = m + logf(s);
    }
    __syncthreads();
    if (tid < kNCls) out[(size_t)row * kNCls + tid] = logits[tid] - s_ls;
}

// ---------------- host launcher ----------------
extern "C" void kernel_launch(void* const* d_in, const int* in_sizes, int n_in,
                              void* d_out, int out_size) {
    const float* x    = (const float*)d_in[0];
    const float* W0   = (const float*)d_in[1];
    const float* b0   = (const float*)d_in[2];
    const float* W1   = (const float*)d_in[3];
    const float* b1   = (const float*)d_in[4];
    const float* W2   = (const float*)d_in[5];
    const float* b2   = (const float*)d_in[6];
    const int*   src0 = (const int*)d_in[7];
    const int*   dst0 = (const int*)d_in[8];
    const int*   src1 = (const int*)d_in[9];
    const int*   dst1 = (const int*)d_in[10];
    const int*   src2 = (const int*)d_in[11];
    const int*   dst2 = (const int*)d_in[12];
    float* out = (float*)d_out;

    float *h0, *h1, *agg2;
    __nv_bfloat16 *w0h, *w0l, *w1h, *w1l;
    int *cnt, *off0, *es0, *off1, *es1, *off2, *es2;
    cudaGetSymbolAddress((void**)&h0,   g_h0);
    cudaGetSymbolAddress((void**)&h1,   g_h1);
    cudaGetSymbolAddress((void**)&agg2, g_agg2);
    cudaGetSymbolAddress((void**)&w0h,  g_w0h);
    cudaGetSymbolAddress((void**)&w0l,  g_w0l);
    cudaGetSymbolAddress((void**)&w1h,  g_w1h);
    cudaGetSymbolAddress((void**)&w1l,  g_w1l);
    cudaGetSymbolAddress((void**)&cnt,  g_cnt);
    cudaGetSymbolAddress((void**)&off0, g_off0);
    cudaGetSymbolAddress((void**)&es0,  g_es0);
    cudaGetSymbolAddress((void**)&off1, g_off1);
    cudaGetSymbolAddress((void**)&es1,  g_es1);
    cudaGetSymbolAddress((void**)&off2, g_off2);
    cudaGetSymbolAddress((void**)&es2,  g_es2);

    cudaFuncSetAttribute(fused_layer_kernel,
                         cudaFuncAttributeMaxDynamicSharedMemorySize, kFusedSmem);

    // CSR build + weight conversion
    cudaMemsetAsync(cnt, 0, 2 * kNDstTot * sizeof(int));
    hist3_kernel<<<(kE0 + 255) / 256, 256>>>(dst0, dst1, dst2);
    exscanA_kernel<<<37, 1024>>>();
    exscanB_kernel<<<37, 1024>>>();
    fill3_kernel<<<(kE0 + 255) / 256, 256>>>(src0, dst0, src1, dst1, src2, dst2);
    wconv_kernel<<<(2 * 65536) / 256, 256>>>(W0, W1);

    // Layer 0: fused aggregate + GEMM + relu
    fused_layer_kernel<<<kN0Dst / 128, 512, kFusedSmem>>>(x, off0, es0, w0h, w0l, b0, h0);
    // Layer 1: fused
    fused_layer_kernel<<<kN1Dst / 128, 512, kFusedSmem>>>(h0, off1, es1, w1h, w1l, b1, h1);
    // Layer 2 + log_softmax
    aggregate_f32_kernel<<<(kN2Dst * 32 + 255) / 256, 256>>>(h1, off2, es2, agg2, kN2Dst);
    layer2_logsoftmax_kernel<<<kN2Dst, 64>>>(agg2, W2, b2, out);

    (void)in_sizes; (void)n_in; (void)out_size;
}

// round 13
// speedup vs baseline: 1.2070x; 1.2070x over previous
#include <cuda_runtime.h>
#include <cuda_bf16.h>
#include <math.h>
#include <stdint.h>

// ---------------- problem constants ----------------
constexpr int kN0Src = 400000, kN0Dst = 32000, kE0 = 320000;
constexpr int kN1Src = 32000,  kN1Dst = 3200,  kE1 = 32000;
constexpr int kN2Src = 3200,   kN2Dst = 1024,  kE2 = 10240;
constexpr int kInF = 256, kHid = 256, kNCls = 47;
constexpr int kNDstTot = kN0Dst + kN1Dst + kN2Dst;

// ---------------- device scratch (no allocs allowed) ----------------
__device__ __align__(256) float g_h0  [kN0Dst * kHid];
__device__ __align__(256) float g_h1  [kN1Dst * kHid];
__device__ __align__(256) float g_agg2[kN2Dst * kHid];

__device__ __align__(256) __nv_bfloat16 g_a_hi[kN0Dst * kHid];
__device__ __align__(256) __nv_bfloat16 g_a_lo[kN0Dst * kHid];
__device__ __align__(256) __nv_bfloat16 g_w0h[kHid * kHid], g_w0l[kHid * kHid];
__device__ __align__(256) __nv_bfloat16 g_w1h[kHid * kHid], g_w1l[kHid * kHid];

__device__ __align__(256) int g_cnt[2 * kNDstTot];   // deg | cur, one memset
__device__ int g_off0[kN0Dst + 1], g_es0[kE0];
__device__ int g_off1[kN1Dst + 1], g_es1[kE1];
__device__ int g_off2[kN2Dst + 1], g_es2[kE2];
__device__ int g_bsum[37];

// ---------------- helpers ----------------
__device__ __forceinline__ uint32_t smem_u32(const void* p) {
    uint32_t a;
    asm("{ .reg .u64 t; cvta.to.shared.u64 t, %1; cvt.u32.u64 %0, t; }" : "=r"(a) : "l"(p));
    return a;
}

__device__ __forceinline__ void ldsm_x4(uint32_t& r0, uint32_t& r1, uint32_t& r2,
                                        uint32_t& r3, uint32_t addr) {
    asm volatile("ldmatrix.sync.aligned.m8n8.x4.shared.b16 {%0,%1,%2,%3}, [%4];"
                 : "=r"(r0), "=r"(r1), "=r"(r2), "=r"(r3) : "r"(addr));
}

__device__ __forceinline__ void mma16816(float c[4], uint32_t a0, uint32_t a1,
                                         uint32_t a2, uint32_t a3,
                                         uint32_t b0, uint32_t b1) {
    asm volatile(
        "mma.sync.aligned.m16n8k16.row.col.f32.bf16.bf16.f32 "
        "{%0,%1,%2,%3},{%4,%5,%6,%7},{%8,%9},{%0,%1,%2,%3};"
        : "+f"(c[0]), "+f"(c[1]), "+f"(c[2]), "+f"(c[3])
        : "r"(a0), "r"(a1), "r"(a2), "r"(a3), "r"(b0), "r"(b1));
}

// ---------------- CSR build ----------------
__global__ void hist3_kernel(const int* __restrict__ d0, const int* __restrict__ d1,
                             const int* __restrict__ d2) {
    int i = blockIdx.x * blockDim.x + threadIdx.x;
    if (i < kE0) atomicAdd(&g_cnt[d0[i]], 1);
    if (i < kE1) atomicAdd(&g_cnt[kN0Dst + d1[i]], 1);
    if (i < kE2) atomicAdd(&g_cnt[kN0Dst + kN1Dst + d2[i]], 1);
}

__global__ void exscanA_kernel() {
    __shared__ int warp_sums[32];
    int b = blockIdx.x;
    const int* cnt; int* off; int n, lb;
    if (b < 32)      { cnt = g_cnt;                    off = g_off0; n = kN0Dst; lb = b; }
    else if (b < 36) { cnt = g_cnt + kN0Dst;           off = g_off1; n = kN1Dst; lb = b - 32; }
    else             { cnt = g_cnt + kN0Dst + kN1Dst;  off = g_off2; n = kN2Dst; lb = 0; }
    int tid = threadIdx.x, lane = tid & 31, wid = tid >> 5;
    int idx = lb * 1024 + tid;
    int orig = (idx < n) ? cnt[idx] : 0;
    int v = orig;
    #pragma unroll
    for (int d = 1; d < 32; d <<= 1) {
        int t = __shfl_up_sync(0xffffffffu, v, d);
        if (lane >= d) v += t;
    }
    if (lane == 31) warp_sums[wid] = v;
    __syncthreads();
    if (wid == 0) {
        int w = warp_sums[lane];
        #pragma unroll
        for (int d = 1; d < 32; d <<= 1) {
            int t = __shfl_up_sync(0xffffffffu, w, d);
            if (lane >= d) w += t;
        }
        warp_sums[lane] = w;
    }
    __syncthreads();
    int incl = v + ((wid > 0) ? warp_sums[wid - 1] : 0);
    if (idx < n) off[idx] = incl - orig;
    if (tid == 1023) g_bsum[b] = incl;
}

__global__ void exscanB_kernel() {
    __shared__ int s_prefix, s_total;
    int b = blockIdx.x;
    int* off; int n, lb, base, nb;
    if (b < 32)      { off = g_off0; n = kN0Dst; base = 0;  nb = 32; lb = b; }
    else if (b < 36) { off = g_off1; n = kN1Dst; base = 32; nb = 4;  lb = b - 32; }
    else             { off = g_off2; n = kN2Dst; base = 36; nb = 1;  lb = 0; }
    int tid = threadIdx.x;
    if (tid < 32) {
        int v = (tid < nb) ? g_bsum[base + tid] : 0;
        int incl = v;
        #pragma unroll
        for (int d = 1; d < 32; d <<= 1) {
            int t = __shfl_up_sync(0xffffffffu, incl, d);
            if (tid >= d) incl += t;
        }
        if (tid == lb)     s_prefix = incl - v;
        if (tid == nb - 1) s_total  = incl;
    }
    __syncthreads();
    int idx = lb * 1024 + tid;
    if (idx < n) off[idx] += s_prefix;
    if (lb == nb - 1 && tid == 1023) off[n] = s_total;
}

__global__ void fill3_kernel(const int* __restrict__ s0, const int* __restrict__ d0,
                             const int* __restrict__ s1, const int* __restrict__ d1,
                             const int* __restrict__ s2, const int* __restrict__ d2) {
    int i = blockIdx.x * blockDim.x + threadIdx.x;
    int* cur = g_cnt + kNDstTot;
    if (i < kE0) { int d = d0[i]; int p = atomicAdd(&cur[d], 1);
                   g_es0[g_off0[d] + p] = s0[i]; }
    if (i < kE1) { int d = d1[i]; int p = atomicAdd(&cur[kN0Dst + d], 1);
                   g_es1[g_off1[d] + p] = s1[i]; }
    if (i < kE2) { int d = d2[i]; int p = atomicAdd(&cur[kN0Dst + kN1Dst + d], 1);
                   g_es2[g_off2[d] + p] = s2[i]; }
}

// ---------------- weight transpose + bf16 hi/lo split -------------------------
__global__ void wconv_kernel(const float* __restrict__ W0, const float* __restrict__ W1) {
    int i = blockIdx.x * blockDim.x + threadIdx.x;
    const float* W = (i < 65536) ? W0 : W1;
    __nv_bfloat16* wh = (i < 65536) ? g_w0h : g_w1h;
    __nv_bfloat16* wl = (i < 65536) ? g_w0l : g_w1l;
    int j = i & 65535;
    int k = j >> 8, n = j & 255;
    float v = W[j];
    __nv_bfloat16 hi = __float2bfloat16(v);
    __nv_bfloat16 lo = __float2bfloat16(v - __bfloat162float(hi));
    wh[n * 256 + k] = hi;
    wl[n * 256 + k] = lo;
}

// ---------------- aggregation (warp per dst; 2-edge unroll; R8 body) ----------
template <int BF16OUT>
__global__ void aggregate_kernel(const float* __restrict__ feat, const int* __restrict__ off,
                                 const int* __restrict__ esrc, float* __restrict__ aggf,
                                 __nv_bfloat16* __restrict__ ah, __nv_bfloat16* __restrict__ al,
                                 int n_dst) {
    int warp = (blockIdx.x * blockDim.x + threadIdx.x) >> 5;
    int lane = threadIdx.x & 31;
    if (warp >= n_dst) return;
    int s = off[warp], e = off[warp + 1];
    float4 a0 = make_float4(0.f, 0.f, 0.f, 0.f);
    float4 a1 = make_float4(0.f, 0.f, 0.f, 0.f);
    for (int i = s; i < e; i += 2) {
        int j0 = __ldg(esrc + i);
        bool two = (i + 1 < e);
        int j1 = two ? __ldg(esrc + i + 1) : j0;
        const float4* r0p = (const float4*)(feat + (size_t)j0 * 256);
        const float4* r1p = (const float4*)(feat + (size_t)j1 * 256);
        float4 u0 = __ldg(&r0p[lane]);
        float4 u1 = __ldg(&r0p[lane + 32]);
        float4 w0 = __ldg(&r1p[lane]);
        float4 w1 = __ldg(&r1p[lane + 32]);
        a0.x += u0.x; a0.y += u0.y; a0.z += u0.z; a0.w += u0.w;
        a1.x += u1.x; a1.y += u1.y; a1.z += u1.z; a1.w += u1.w;
        if (two) {
            a0.x += w0.x; a0.y += w0.y; a0.z += w0.z; a0.w += w0.w;
            a1.x += w1.x; a1.y += w1.y; a1.z += w1.z; a1.w += w1.w;
        }
    }
    int deg = e - s;
    float inv = 1.0f / (float)(deg > 1 ? deg : 1);
    a0.x *= inv; a0.y *= inv; a0.z *= inv; a0.w *= inv;
    a1.x *= inv; a1.y *= inv; a1.z *= inv; a1.w *= inv;
    if (BF16OUT) {
        float v[8] = {a0.x, a0.y, a0.z, a0.w, a1.x, a1.y, a1.z, a1.w};
        #pragma unroll
        for (int g = 0; g < 2; g++) {
            __nv_bfloat162 h01, h23, l01, l23;
            h01.x = __float2bfloat16(v[g*4+0]); h01.y = __float2bfloat16(v[g*4+1]);
            h23.x = __float2bfloat16(v[g*4+2]); h23.y = __float2bfloat16(v[g*4+3]);
            l01.x = __float2bfloat16(v[g*4+0] - __bfloat162float(h01.x));
            l01.y = __float2bfloat16(v[g*4+1] - __bfloat162float(h01.y));
            l23.x = __float2bfloat16(v[g*4+2] - __bfloat162float(h23.x));
            l23.y = __float2bfloat16(v[g*4+3] - __bfloat162float(h23.y));
            size_t base = (size_t)warp * 256 + g * 128 + lane * 4;
            *(__nv_bfloat162*)(ah + base)     = h01;
            *(__nv_bfloat162*)(ah + base + 2) = h23;
            *(__nv_bfloat162*)(al + base)     = l01;
            *(__nv_bfloat162*)(al + base + 2) = l23;
        }
    } else {
        float4* dp = (float4*)(aggf + (size_t)warp * 256);
        dp[lane]      = a0;
        dp[lane + 32] = a1;
    }
}

// ---------------- bf16 mma.sync GEMM with 3-product split ---------------------
// Grid = (2, M/128): the two N-half CTAs sharing the same A rows are ADJACENT
// in launch order -> co-resident -> the second one's A loads hit L2.
constexpr int SA_HI = 0;
constexpr int SA_LO = 16384;
constexpr int SB_HI = 32768;
constexpr int SB_LO = 49152;
constexpr int kGemmSmem = 65536;

__global__ void __launch_bounds__(256)
gemm_mma_relu_kernel(const __nv_bfloat16* __restrict__ Ah, const __nv_bfloat16* __restrict__ Al,
                     const __nv_bfloat16* __restrict__ Bh, const __nv_bfloat16* __restrict__ Bl,
                     const float* __restrict__ bias, float* __restrict__ C) {
    extern __shared__ char smem[];
    uint32_t sb = smem_u32(smem);
    int tid = threadIdx.x, warp = tid >> 5, lane = tid & 31;
    int m0 = blockIdx.y * 128;   // M tile (slow axis)
    int n0 = blockIdx.x * 128;   // N tile (fast axis; twins adjacent)
    int wm = (warp & 3) * 32;
    int wn = (warp >> 2) * 64;

    float acc[2][8][4];
    #pragma unroll
    for (int i = 0; i < 2; i++)
        #pragma unroll
        for (int j = 0; j < 8; j++)
            #pragma unroll
            for (int q = 0; q < 4; q++) acc[i][j][q] = 0.f;

    uint32_t xorv = (uint32_t)(lane & 7) << 4;
    int rowA = wm + (lane & 7) + ((lane >> 3) & 1) * 8;
    uint32_t kbA = ((lane >> 4) & 1) << 4;
    uint32_t pA0 = sb + SA_HI + (uint32_t)(rowA)      * 128;
    uint32_t pA1 = sb + SA_HI + (uint32_t)(rowA + 16) * 128;
    int rowB = wn + (lane & 7) + ((lane >> 4) & 1) * 8;
    uint32_t kbB = ((lane >> 3) & 1) << 4;
    uint32_t pB[4];
    #pragma unroll
    for (int j16 = 0; j16 < 4; j16++)
        pB[j16] = sb + SB_HI + (uint32_t)(rowB + j16 * 16) * 128;

    #pragma unroll 1
    for (int kc = 0; kc < 4; kc++) {
        #pragma unroll
        for (int u = tid; u < 1024; u += 256) {
            int row = u >> 3;
            uint32_t c16 = (u & 7) << 4;
            uint32_t so = (uint32_t)row * 128 + (c16 ^ ((row & 7) << 4));
            size_t ga = (size_t)(m0 + row) * 256 + kc * 64 + (c16 >> 1);
            size_t gb = (size_t)(n0 + row) * 256 + kc * 64 + (c16 >> 1);
            *(uint4*)(smem + SA_HI + so) = *(const uint4*)(Ah + ga);
            *(uint4*)(smem + SA_LO + so) = *(const uint4*)(Al + ga);
            *(uint4*)(smem + SB_HI + so) = *(const uint4*)(Bh + gb);
            *(uint4*)(smem + SB_LO + so) = *(const uint4*)(Bl + gb);
        }
        __syncthreads();

        #pragma unroll
        for (int kk = 0; kk < 4; kk++) {
            uint32_t koA = ((uint32_t)kk * 32 + kbA) ^ xorv;
            uint32_t koB = ((uint32_t)kk * 32 + kbB) ^ xorv;
            uint32_t ah[2][4], al[2][4];
            ldsm_x4(ah[0][0], ah[0][1], ah[0][2], ah[0][3], pA0 + koA);
            ldsm_x4(ah[1][0], ah[1][1], ah[1][2], ah[1][3], pA1 + koA);
            ldsm_x4(al[0][0], al[0][1], al[0][2], al[0][3], pA0 + 16384 + koA);
            ldsm_x4(al[1][0], al[1][1], al[1][2], al[1][3], pA1 + 16384 + koA);
            #pragma unroll
            for (int j16 = 0; j16 < 4; j16++) {
                uint32_t bh0, bh1, bh2, bh3, bl0, bl1, bl2, bl3;
                ldsm_x4(bh0, bh1, bh2, bh3, pB[j16] + koB);
                ldsm_x4(bl0, bl1, bl2, bl3, pB[j16] + 16384 + koB);
                #pragma unroll
                for (int i = 0; i < 2; i++) {
                    mma16816(acc[i][2*j16+0], ah[i][0], ah[i][1], ah[i][2], ah[i][3], bh0, bh1);
                    mma16816(acc[i][2*j16+0], al[i][0], al[i][1], al[i][2], al[i][3], bh0, bh1);
                    mma16816(acc[i][2*j16+0], ah[i][0], ah[i][1], ah[i][2], ah[i][3], bl0, bl1);
                    mma16816(acc[i][2*j16+1], ah[i][0], ah[i][1], ah[i][2], ah[i][3], bh2, bh3);
                    mma16816(acc[i][2*j16+1], al[i][0], al[i][1], al[i][2], al[i][3], bh2, bh3);
                    mma16816(acc[i][2*j16+1], ah[i][0], ah[i][1], ah[i][2], ah[i][3], bl2, bl3);
                }
            }
        }
        __syncthreads();
    }

    // ---- epilogue ----
    int qr = lane >> 2;
    int qc = (lane & 3) << 1;
    #pragma unroll
    for (int i = 0; i < 2; i++) {
        int r0 = m0 + wm + i * 16 + qr;
        #pragma unroll
        for (int j = 0; j < 8; j++) {
            int col = n0 + wn + j * 8 + qc;
            float b0 = __ldg(bias + col), b1 = __ldg(bias + col + 1);
            float2 v0, v1;
            v0.x = fmaxf(acc[i][j][0] + b0, 0.f);
            v0.y = fmaxf(acc[i][j][1] + b1, 0.f);
            v1.x = fmaxf(acc[i][j][2] + b0, 0.f);
            v1.y = fmaxf(acc[i][j][3] + b1, 0.f);
            *(float2*)(C + (size_t)r0 * 256 + col)       = v0;
            *(float2*)(C + (size_t)(r0 + 8) * 256 + col) = v1;
        }
    }
}

// ---------------- layer 2 + log_softmax ----------------
__global__ void layer2_logsoftmax_kernel(const float* __restrict__ agg,
                                         const float* __restrict__ W,
                                         const float* __restrict__ b,
                                         float* __restrict__ out) {
    __shared__ float a[256];
    __shared__ float logits[kNCls];
    __shared__ float s_ls;
    int row = blockIdx.x;
    int tid = threadIdx.x;
    const float4* ap = (const float4*)(agg + (size_t)row * 256);
    ((float4*)a)[tid] = ap[tid];
    __syncthreads();
    if (tid < kNCls) {
        float sum = b[tid];
        #pragma unroll 8
        for (int k = 0; k < 256; k++) sum += a[k] * W[k * kNCls + tid];
        logits[tid] = sum;
    }
    __syncthreads();
    if (tid == 0) {
        float m = -INFINITY;
        for (int j = 0; j < kNCls; j++) m = fmaxf(m, logits[j]);
        float s = 0.f;
        for (int j = 0; j < kNCls; j++) s += expf(logits[j] - m);
        s_ls = m + logf(s);
    }
    __syncthreads();
    if (tid < kNCls) out[(size_t)row * kNCls + tid] = logits[tid] - s_ls;
}

// ---------------- host launcher ----------------
extern "C" void kernel_launch(void* const* d_in, const int* in_sizes, int n_in,
                              void* d_out, int out_size) {
    const float* x    = (const float*)d_in[0];
    const float* W0   = (const float*)d_in[1];
    const float* b0   = (const float*)d_in[2];
    const float* W1   = (const float*)d_in[3];
    const float* b1   = (const float*)d_in[4];
    const float* W2   = (const float*)d_in[5];
    const float* b2   = (const float*)d_in[6];
    const int*   src0 = (const int*)d_in[7];
    const int*   dst0 = (const int*)d_in[8];
    const int*   src1 = (const int*)d_in[9];
    const int*   dst1 = (const int*)d_in[10];
    const int*   src2 = (const int*)d_in[11];
    const int*   dst2 = (const int*)d_in[12];
    float* out = (float*)d_out;

    float *h0, *h1, *agg2;
    __nv_bfloat16 *ahi, *alo, *w0h, *w0l, *w1h, *w1l;
    int *cnt, *off0, *es0, *off1, *es1, *off2, *es2;
    cudaGetSymbolAddress((void**)&h0,   g_h0);
    cudaGetSymbolAddress((void**)&h1,   g_h1);
    cudaGetSymbolAddress((void**)&agg2, g_agg2);
    cudaGetSymbolAddress((void**)&ahi,  g_a_hi);
    cudaGetSymbolAddress((void**)&alo,  g_a_lo);
    cudaGetSymbolAddress((void**)&w0h,  g_w0h);
    cudaGetSymbolAddress((void**)&w0l,  g_w0l);
    cudaGetSymbolAddress((void**)&w1h,  g_w1h);
    cudaGetSymbolAddress((void**)&w1l,  g_w1l);
    cudaGetSymbolAddress((void**)&cnt,  g_cnt);
    cudaGetSymbolAddress((void**)&off0, g_off0);
    cudaGetSymbolAddress((void**)&es0,  g_es0);
    cudaGetSymbolAddress((void**)&off1, g_off1);
    cudaGetSymbolAddress((void**)&es1,  g_es1);
    cudaGetSymbolAddress((void**)&off2, g_off2);
    cudaGetSymbolAddress((void**)&es2,  g_es2);

    cudaFuncSetAttribute(gemm_mma_relu_kernel,
                         cudaFuncAttributeMaxDynamicSharedMemorySize, kGemmSmem);

    // CSR build + weight conversion
    cudaMemsetAsync(cnt, 0, 2 * kNDstTot * sizeof(int));
    hist3_kernel<<<(kE0 + 255) / 256, 256>>>(dst0, dst1, dst2);
    exscanA_kernel<<<37, 1024>>>();
    exscanB_kernel<<<37, 1024>>>();
    fill3_kernel<<<(kE0 + 255) / 256, 256>>>(src0, dst0, src1, dst1, src2, dst2);

    // Layer 0
    aggregate_kernel<1><<<(kN0Dst * 32 + 255) / 256, 256>>>(
        x, off0, es0, nullptr, ahi, alo, kN0Dst);
    wconv_kernel<<<(2 * 65536) / 256, 256>>>(W0, W1);
    {
        dim3 grid(2, kN0Dst / 128);
        gemm_mma_relu_kernel<<<grid, 256, kGemmSmem>>>(ahi, alo, w0h, w0l, b0, h0);
    }
    // Layer 1
    aggregate_kernel<1><<<(kN1Dst * 32 + 255) / 256, 256>>>(h0, off1, es1, nullptr, ahi, alo, kN1Dst);
    {
        dim3 grid(2, kN1Dst / 128);
        gemm_mma_relu_kernel<<<grid, 256, kGemmSmem>>>(ahi, alo, w1h, w1l, b1, h1);
    }
    // Layer 2 + log_softmax
    aggregate_kernel<0><<<(kN2Dst * 32 + 255) / 256, 256>>>(h1, off2, es2, agg2, nullptr, nullptr, kN2Dst);
    layer2_logsoftmax_kernel<<<kN2Dst, 64>>>(agg2, W2, b2, out);

    (void)in_sizes; (void)n_in; (void)out_size;
}

// round 14
// speedup vs baseline: 1.2291x; 1.0184x over previous
#include <cuda_runtime.h>
#include <cuda_bf16.h>
#include <math.h>
#include <stdint.h>

// ---------------- problem constants ----------------
constexpr int kN0Src = 400000, kN0Dst = 32000, kE0 = 320000;
constexpr int kN1Src = 32000,  kN1Dst = 3200,  kE1 = 32000;
constexpr int kN2Src = 3200,   kN2Dst = 1024,  kE2 = 10240;
constexpr int kInF = 256, kHid = 256, kNCls = 47;
constexpr int kNDstTot = kN0Dst + kN1Dst + kN2Dst;

// ---------------- device scratch (no allocs allowed) ----------------
__device__ __align__(256) float g_h0  [kN0Dst * kHid];
__device__ __align__(256) float g_h1  [kN1Dst * kHid];
__device__ __align__(256) float g_agg2[kN2Dst * kHid];

__device__ __align__(256) __nv_bfloat16 g_a_hi[kN0Dst * kHid];
__device__ __align__(256) __nv_bfloat16 g_a_lo[kN0Dst * kHid];
__device__ __align__(256) __nv_bfloat16 g_w0h[kHid * kHid], g_w0l[kHid * kHid];
__device__ __align__(256) __nv_bfloat16 g_w1h[kHid * kHid], g_w1l[kHid * kHid];

__device__ __align__(256) int g_cnt[2 * kNDstTot];   // deg | cur, one memset
__device__ int g_off0[kN0Dst + 1], g_es0[kE0];
__device__ int g_off1[kN1Dst + 1], g_es1[kE1];
__device__ int g_off2[kN2Dst + 1], g_es2[kE2];
__device__ int g_bsum[37];

// ---------------- helpers ----------------
__device__ __forceinline__ uint32_t smem_u32(const void* p) {
    uint32_t a;
    asm("{ .reg .u64 t; cvta.to.shared.u64 t, %1; cvt.u32.u64 %0, t; }" : "=r"(a) : "l"(p));
    return a;
}

__device__ __forceinline__ void ldsm_x4(uint32_t& r0, uint32_t& r1, uint32_t& r2,
                                        uint32_t& r3, uint32_t addr) {
    asm volatile("ldmatrix.sync.aligned.m8n8.x4.shared.b16 {%0,%1,%2,%3}, [%4];"
                 : "=r"(r0), "=r"(r1), "=r"(r2), "=r"(r3) : "r"(addr));
}

__device__ __forceinline__ void mma16816(float c[4], uint32_t a0, uint32_t a1,
                                         uint32_t a2, uint32_t a3,
                                         uint32_t b0, uint32_t b1) {
    asm volatile(
        "mma.sync.aligned.m16n8k16.row.col.f32.bf16.bf16.f32 "
        "{%0,%1,%2,%3},{%4,%5,%6,%7},{%8,%9},{%0,%1,%2,%3};"
        : "+f"(c[0]), "+f"(c[1]), "+f"(c[2]), "+f"(c[3])
        : "r"(a0), "r"(a1), "r"(a2), "r"(a3), "r"(b0), "r"(b1));
}

// ---------------- CSR build ----------------
__global__ void hist3_kernel(const int* __restrict__ d0, const int* __restrict__ d1,
                             const int* __restrict__ d2) {
    int i = blockIdx.x * blockDim.x + threadIdx.x;
    if (i < kE0) atomicAdd(&g_cnt[d0[i]], 1);
    if (i < kE1) atomicAdd(&g_cnt[kN0Dst + d1[i]], 1);
    if (i < kE2) atomicAdd(&g_cnt[kN0Dst + kN1Dst + d2[i]], 1);
}

__global__ void exscanA_kernel() {
    __shared__ int warp_sums[32];
    int b = blockIdx.x;
    const int* cnt; int* off; int n, lb;
    if (b < 32)      { cnt = g_cnt;                    off = g_off0; n = kN0Dst; lb = b; }
    else if (b < 36) { cnt = g_cnt + kN0Dst;           off = g_off1; n = kN1Dst; lb = b - 32; }
    else             { cnt = g_cnt + kN0Dst + kN1Dst;  off = g_off2; n = kN2Dst; lb = 0; }
    int tid = threadIdx.x, lane = tid & 31, wid = tid >> 5;
    int idx = lb * 1024 + tid;
    int orig = (idx < n) ? cnt[idx] : 0;
    int v = orig;
    #pragma unroll
    for (int d = 1; d < 32; d <<= 1) {
        int t = __shfl_up_sync(0xffffffffu, v, d);
        if (lane >= d) v += t;
    }
    if (lane == 31) warp_sums[wid] = v;
    __syncthreads();
    if (wid == 0) {
        int w = warp_sums[lane];
        #pragma unroll
        for (int d = 1; d < 32; d <<= 1) {
            int t = __shfl_up_sync(0xffffffffu, w, d);
            if (lane >= d) w += t;
        }
        warp_sums[lane] = w;
    }
    __syncthreads();
    int incl = v + ((wid > 0) ? warp_sums[wid - 1] : 0);
    if (idx < n) off[idx] = incl - orig;
    if (tid == 1023) g_bsum[b] = incl;
}

__global__ void exscanB_kernel() {
    __shared__ int s_prefix, s_total;
    int b = blockIdx.x;
    int* off; int n, lb, base, nb;
    if (b < 32)      { off = g_off0; n = kN0Dst; base = 0;  nb = 32; lb = b; }
    else if (b < 36) { off = g_off1; n = kN1Dst; base = 32; nb = 4;  lb = b - 32; }
    else             { off = g_off2; n = kN2Dst; base = 36; nb = 1;  lb = 0; }
    int tid = threadIdx.x;
    if (tid < 32) {
        int v = (tid < nb) ? g_bsum[base + tid] : 0;
        int incl = v;
        #pragma unroll
        for (int d = 1; d < 32; d <<= 1) {
            int t = __shfl_up_sync(0xffffffffu, incl, d);
            if (tid >= d) incl += t;
        }
        if (tid == lb)     s_prefix = incl - v;
        if (tid == nb - 1) s_total  = incl;
    }
    __syncthreads();
    int idx = lb * 1024 + tid;
    if (idx < n) off[idx] += s_prefix;
    if (lb == nb - 1 && tid == 1023) off[n] = s_total;
}

__global__ void fill3_kernel(const int* __restrict__ s0, const int* __restrict__ d0,
                             const int* __restrict__ s1, const int* __restrict__ d1,
                             const int* __restrict__ s2, const int* __restrict__ d2) {
    int i = blockIdx.x * blockDim.x + threadIdx.x;
    int* cur = g_cnt + kNDstTot;
    if (i < kE0) { int d = d0[i]; int p = atomicAdd(&cur[d], 1);
                   g_es0[g_off0[d] + p] = s0[i]; }
    if (i < kE1) { int d = d1[i]; int p = atomicAdd(&cur[kN0Dst + d], 1);
                   g_es1[g_off1[d] + p] = s1[i]; }
    if (i < kE2) { int d = d2[i]; int p = atomicAdd(&cur[kN0Dst + kN1Dst + d], 1);
                   g_es2[g_off2[d] + p] = s2[i]; }
}

// ---------------- weight transpose + bf16 hi/lo split -------------------------
__global__ void wconv_kernel(const float* __restrict__ W0, const float* __restrict__ W1) {
    int i = blockIdx.x * blockDim.x + threadIdx.x;
    const float* W = (i < 65536) ? W0 : W1;
    __nv_bfloat16* wh = (i < 65536) ? g_w0h : g_w1h;
    __nv_bfloat16* wl = (i < 65536) ? g_w0l : g_w1l;
    int j = i & 65535;
    int k = j >> 8, n = j & 255;
    float v = W[j];
    __nv_bfloat16 hi = __float2bfloat16(v);
    __nv_bfloat16 lo = __float2bfloat16(v - __bfloat162float(hi));
    wh[n * 256 + k] = hi;
    wl[n * 256 + k] = lo;
}

// ---------------- aggregation (warp per dst; 2-edge unroll) -------------------
template <int BF16OUT>
__global__ void aggregate_kernel(const float* __restrict__ feat, const int* __restrict__ off,
                                 const int* __restrict__ esrc, float* __restrict__ aggf,
                                 __nv_bfloat16* __restrict__ ah, __nv_bfloat16* __restrict__ al,
                                 int n_dst) {
    int warp = (blockIdx.x * blockDim.x + threadIdx.x) >> 5;
    int lane = threadIdx.x & 31;
    if (warp >= n_dst) return;
    int s = off[warp], e = off[warp + 1];
    float4 a0 = make_float4(0.f, 0.f, 0.f, 0.f);
    float4 a1 = make_float4(0.f, 0.f, 0.f, 0.f);
    for (int i = s; i < e; i += 2) {
        int j0 = __ldg(esrc + i);
        bool two = (i + 1 < e);
        int j1 = two ? __ldg(esrc + i + 1) : j0;
        const float4* r0p = (const float4*)(feat + (size_t)j0 * 256);
        const float4* r1p = (const float4*)(feat + (size_t)j1 * 256);
        float4 u0 = __ldg(&r0p[lane]);
        float4 u1 = __ldg(&r0p[lane + 32]);
        float4 w0 = __ldg(&r1p[lane]);
        float4 w1 = __ldg(&r1p[lane + 32]);
        a0.x += u0.x; a0.y += u0.y; a0.z += u0.z; a0.w += u0.w;
        a1.x += u1.x; a1.y += u1.y; a1.z += u1.z; a1.w += u1.w;
        if (two) {
            a0.x += w0.x; a0.y += w0.y; a0.z += w0.z; a0.w += w0.w;
            a1.x += w1.x; a1.y += w1.y; a1.z += w1.z; a1.w += w1.w;
        }
    }
    int deg = e - s;
    float inv = 1.0f / (float)(deg > 1 ? deg : 1);
    a0.x *= inv; a0.y *= inv; a0.z *= inv; a0.w *= inv;
    a1.x *= inv; a1.y *= inv; a1.z *= inv; a1.w *= inv;
    if (BF16OUT) {
        float v[8] = {a0.x, a0.y, a0.z, a0.w, a1.x, a1.y, a1.z, a1.w};
        #pragma unroll
        for (int g = 0; g < 2; g++) {
            __nv_bfloat162 h01, h23, l01, l23;
            h01.x = __float2bfloat16(v[g*4+0]); h01.y = __float2bfloat16(v[g*4+1]);
            h23.x = __float2bfloat16(v[g*4+2]); h23.y = __float2bfloat16(v[g*4+3]);
            l01.x = __float2bfloat16(v[g*4+0] - __bfloat162float(h01.x));
            l01.y = __float2bfloat16(v[g*4+1] - __bfloat162float(h01.y));
            l23.x = __float2bfloat16(v[g*4+2] - __bfloat162float(h23.x));
            l23.y = __float2bfloat16(v[g*4+3] - __bfloat162float(h23.y));
            size_t base = (size_t)warp * 256 + g * 128 + lane * 4;
            *(__nv_bfloat162*)(ah + base)     = h01;
            *(__nv_bfloat162*)(ah + base + 2) = h23;
            *(__nv_bfloat162*)(al + base)     = l01;
            *(__nv_bfloat162*)(al + base + 2) = l23;
        }
    } else {
        float4* dp = (float4*)(aggf + (size_t)warp * 256);
        dp[lane]      = a0;
        dp[lane + 32] = a1;
    }
}

// ---------------- bf16 mma.sync GEMM with 3-product split ---------------------
constexpr int SA_HI = 0;
constexpr int SA_LO = 16384;
constexpr int SB_HI = 32768;
constexpr int SB_LO = 49152;
constexpr int kGemmSmem = 65536;

__global__ void __launch_bounds__(256)
gemm_mma_relu_kernel(const __nv_bfloat16* __restrict__ Ah, const __nv_bfloat16* __restrict__ Al,
                     const __nv_bfloat16* __restrict__ Bh, const __nv_bfloat16* __restrict__ Bl,
                     const float* __restrict__ bias, float* __restrict__ C) {
    extern __shared__ char smem[];
    uint32_t sb = smem_u32(smem);
    int tid = threadIdx.x, warp = tid >> 5, lane = tid & 31;
    int m0 = blockIdx.x * 128;
    int n0 = blockIdx.y * 128;
    int wm = (warp & 3) * 32;
    int wn = (warp >> 2) * 64;

    float acc[2][8][4];
    #pragma unroll
    for (int i = 0; i < 2; i++)
        #pragma unroll
        for (int j = 0; j < 8; j++)
            #pragma unroll
            for (int q = 0; q < 4; q++) acc[i][j][q] = 0.f;

    uint32_t xorv = (uint32_t)(lane & 7) << 4;
    int rowA = wm + (lane & 7) + ((lane >> 3) & 1) * 8;
    uint32_t kbA = ((lane >> 4) & 1) << 4;
    uint32_t pA0 = sb + SA_HI + (uint32_t)(rowA)      * 128;
    uint32_t pA1 = sb + SA_HI + (uint32_t)(rowA + 16) * 128;
    int rowB = wn + (lane & 7) + ((lane >> 4) & 1) * 8;
    uint32_t kbB = ((lane >> 3) & 1) << 4;
    uint32_t pB[4];
    #pragma unroll
    for (int j16 = 0; j16 < 4; j16++)
        pB[j16] = sb + SB_HI + (uint32_t)(rowB + j16 * 16) * 128;

    #pragma unroll 1
    for (int kc = 0; kc < 4; kc++) {
        #pragma unroll
        for (int u = tid; u < 1024; u += 256) {
            int row = u >> 3;
            uint32_t c16 = (u & 7) << 4;
            uint32_t so = (uint32_t)row * 128 + (c16 ^ ((row & 7) << 4));
            size_t ga = (size_t)(m0 + row) * 256 + kc * 64 + (c16 >> 1);
            size_t gb = (size_t)(n0 + row) * 256 + kc * 64 + (c16 >> 1);
            *(uint4*)(smem + SA_HI + so) = *(const uint4*)(Ah + ga);
            *(uint4*)(smem + SA_LO + so) = *(const uint4*)(Al + ga);
            *(uint4*)(smem + SB_HI + so) = *(const uint4*)(Bh + gb);
            *(uint4*)(smem + SB_LO + so) = *(const uint4*)(Bl + gb);
        }
        __syncthreads();

        #pragma unroll
        for (int kk = 0; kk < 4; kk++) {
            uint32_t koA = ((uint32_t)kk * 32 + kbA) ^ xorv;
            uint32_t koB = ((uint32_t)kk * 32 + kbB) ^ xorv;
            uint32_t ah[2][4], al[2][4];
            ldsm_x4(ah[0][0], ah[0][1], ah[0][2], ah[0][3], pA0 + koA);
            ldsm_x4(ah[1][0], ah[1][1], ah[1][2], ah[1][3], pA1 + koA);
            ldsm_x4(al[0][0], al[0][1], al[0][2], al[0][3], pA0 + 16384 + koA);
            ldsm_x4(al[1][0], al[1][1], al[1][2], al[1][3], pA1 + 16384 + koA);
            #pragma unroll
            for (int j16 = 0; j16 < 4; j16++) {
                uint32_t bh0, bh1, bh2, bh3, bl0, bl1, bl2, bl3;
                ldsm_x4(bh0, bh1, bh2, bh3, pB[j16] + koB);
                ldsm_x4(bl0, bl1, bl2, bl3, pB[j16] + 16384 + koB);
                #pragma unroll
                for (int i = 0; i < 2; i++) {
                    mma16816(acc[i][2*j16+0], ah[i][0], ah[i][1], ah[i][2], ah[i][3], bh0, bh1);
                    mma16816(acc[i][2*j16+0], al[i][0], al[i][1], al[i][2], al[i][3], bh0, bh1);
                    mma16816(acc[i][2*j16+0], ah[i][0], ah[i][1], ah[i][2], ah[i][3], bl0, bl1);
                    mma16816(acc[i][2*j16+1], ah[i][0], ah[i][1], ah[i][2], ah[i][3], bh2, bh3);
                    mma16816(acc[i][2*j16+1], al[i][0], al[i][1], al[i][2], al[i][3], bh2, bh3);
                    mma16816(acc[i][2*j16+1], ah[i][0], ah[i][1], ah[i][2], ah[i][3], bl2, bl3);
                }
            }
        }
        __syncthreads();
    }

    // ---- epilogue ----
    int qr = lane >> 2;
    int qc = (lane & 3) << 1;
    #pragma unroll
    for (int i = 0; i < 2; i++) {
        int r0 = m0 + wm + i * 16 + qr;
        #pragma unroll
        for (int j = 0; j < 8; j++) {
            int col = n0 + wn + j * 8 + qc;
            float b0 = __ldg(bias + col), b1 = __ldg(bias + col + 1);
            float2 v0, v1;
            v0.x = fmaxf(acc[i][j][0] + b0, 0.f);
            v0.y = fmaxf(acc[i][j][1] + b1, 0.f);
            v1.x = fmaxf(acc[i][j][2] + b0, 0.f);
            v1.y = fmaxf(acc[i][j][3] + b1, 0.f);
            *(float2*)(C + (size_t)r0 * 256 + col)       = v0;
            *(float2*)(C + (size_t)(r0 + 8) * 256 + col) = v1;
        }
    }
}

// ---------------- layer 2 + log_softmax ----------------
__global__ void layer2_logsoftmax_kernel(const float* __restrict__ agg,
                                         const float* __restrict__ W,
                                         const float* __restrict__ b,
                                         float* __restrict__ out) {
    __shared__ float a[256];
    __shared__ float logits[kNCls];
    __shared__ float s_ls;
    int row = blockIdx.x;
    int tid = threadIdx.x;
    const float4* ap = (const float4*)(agg + (size_t)row * 256);
    ((float4*)a)[tid] = ap[tid];
    __syncthreads();
    if (tid < kNCls) {
        float sum = b[tid];
        #pragma unroll 8
        for (int k = 0; k < 256; k++) sum += a[k] * W[k * kNCls + tid];
        logits[tid] = sum;
    }
    __syncthreads();
    if (tid == 0) {
        float m = -INFINITY;
        for (int j = 0; j < kNCls; j++) m = fmaxf(m, logits[j]);
        float s = 0.f;
        for (int j = 0; j < kNCls; j++) s += expf(logits[j] - m);
        s_ls = m + logf(s);
    }
    __syncthreads();
    if (tid < kNCls) out[(size_t)row * kNCls + tid] = logits[tid] - s_ls;
}

// ---------------- host launcher ----------------
extern "C" void kernel_launch(void* const* d_in, const int* in_sizes, int n_in,
                              void* d_out, int out_size) {
    const float* x    = (const float*)d_in[0];
    const float* W0   = (const float*)d_in[1];
    const float* b0   = (const float*)d_in[2];
    const float* W1   = (const float*)d_in[3];
    const float* b1   = (const float*)d_in[4];
    const float* W2   = (const float*)d_in[5];
    const float* b2   = (const float*)d_in[6];
    const int*   src0 = (const int*)d_in[7];
    const int*   dst0 = (const int*)d_in[8];
    const int*   src1 = (const int*)d_in[9];
    const int*   dst1 = (const int*)d_in[10];
    const int*   src2 = (const int*)d_in[11];
    const int*   dst2 = (const int*)d_in[12];
    float* out = (float*)d_out;

    float *h0, *h1, *agg2;
    __nv_bfloat16 *ahi, *alo, *w0h, *w0l, *w1h, *w1l;
    int *cnt, *off0, *es0, *off1, *es1, *off2, *es2;
    cudaGetSymbolAddress((void**)&h0,   g_h0);
    cudaGetSymbolAddress((void**)&h1,   g_h1);
    cudaGetSymbolAddress((void**)&agg2, g_agg2);
    cudaGetSymbolAddress((void**)&ahi,  g_a_hi);
    cudaGetSymbolAddress((void**)&alo,  g_a_lo);
    cudaGetSymbolAddress((void**)&w0h,  g_w0h);
    cudaGetSymbolAddress((void**)&w0l,  g_w0l);
    cudaGetSymbolAddress((void**)&w1h,  g_w1h);
    cudaGetSymbolAddress((void**)&w1l,  g_w1l);
    cudaGetSymbolAddress((void**)&cnt,  g_cnt);
    cudaGetSymbolAddress((void**)&off0, g_off0);
    cudaGetSymbolAddress((void**)&es0,  g_es0);
    cudaGetSymbolAddress((void**)&off1, g_off1);
    cudaGetSymbolAddress((void**)&es1,  g_es1);
    cudaGetSymbolAddress((void**)&off2, g_off2);
    cudaGetSymbolAddress((void**)&es2,  g_es2);

    cudaFuncSetAttribute(gemm_mma_relu_kernel,
                         cudaFuncAttributeMaxDynamicSharedMemorySize, kGemmSmem);

    // CSR build
    cudaMemsetAsync(cnt, 0, 2 * kNDstTot * sizeof(int));
    hist3_kernel<<<(kE0 + 255) / 256, 256>>>(dst0, dst1, dst2);
    exscanA_kernel<<<37, 1024>>>();
    exscanB_kernel<<<37, 1024>>>();
    fill3_kernel<<<(kE0 + 255) / 256, 256>>>(src0, dst0, src1, dst1, src2, dst2);

    // Layer 0
    aggregate_kernel<1><<<(kN0Dst * 32 + 255) / 256, 256>>>(
        x, off0, es0, nullptr, ahi, alo, kN0Dst);
    wconv_kernel<<<(2 * 65536) / 256, 256>>>(W0, W1);
    {
        dim3 grid(kN0Dst / 128, 2);
        gemm_mma_relu_kernel<<<grid, 256, kGemmSmem>>>(ahi, alo, w0h, w0l, b0, h0);
    }
    // Layer 1
    aggregate_kernel<1><<<(kN1Dst * 32 + 255) / 256, 256>>>(h0, off1, es1, nullptr, ahi, alo, kN1Dst);
    {
        dim3 grid(kN1Dst / 128, 2);
        gemm_mma_relu_kernel<<<grid, 256, kGemmSmem>>>(ahi, alo, w1h, w1l, b1, h1);
    }
    // Layer 2 + log_softmax
    aggregate_kernel<0><<<(kN2Dst * 32 + 255) / 256, 256>>>(h1, off2, es2, agg2, nullptr, nullptr, kN2Dst);
    layer2_logsoftmax_kernel<<<kN2Dst, 64>>>(agg2, W2, b2, out);

    (void)in_sizes; (void)n_in; (void)out_size;
}